// round 15
// baseline (speedup 1.0000x reference)
#include <cuda_runtime.h>
#include <cuda_fp16.h>
#include <cstdint>

#define Bn   8
#define CIn  512
#define COn  512
#define WDn  512
#define Hn   64
#define HPn  66
#define RS   72                  // padded row stride (halves), 144B = 16B aligned
#define PS   (HPn*RS)            // plane stride in halves (4752)
#define KTOT 4608
#define KP   1536                // K per ky-pass (ci*3)

// conv tiling
#define TM   128                 // co per CTA
#define TN   128                 // hw per CTA (2 image rows)
#define KT   96                  // K per stage = 32 ci x 3 kx
#define NSTAGE 48                // 3 passes x 16 stages
#define A_STRIDE 208             // 192B data + 16B pad (conflict-free ldmatrix: 80*l mod 128 distinct)
#define AS_B (TM*A_STRIDE)       // 26624
#define BS_B (KT*256)            // 24576
#define STG  (AS_B + BS_B)       // 51200
#define SMEM_TOTAL (2*STG)       // 102400 (dynamic); x2 CTAs = 200 KB/SM
#define NT   256                 // threads per CTA (8 warps, 2x4, 64x32 warp tiles)

// ---------------- scratch (device globals; no allocations) ----------------
static __device__ float  g_s[Bn*CIn];
// weights reordered: [b][ky][co][ci*3+kx], fp16
static __device__ __align__(16) __half g_wt[(size_t)Bn*3*COn*KP];
// padded input, row stride 72: [b*CI + ci][row][72]
static __device__ __align__(16) __half g_xpad[(size_t)Bn*CIn*PS];

// ---------------- PTX helpers ----------------
__device__ __forceinline__ uint32_t smem_u32(const void* p) {
    uint32_t a;
    asm("{ .reg .u64 t; cvta.to.shared.u64 t, %1; cvt.u32.u64 %0, t; }" : "=r"(a) : "l"(p));
    return a;
}
__device__ __forceinline__ void cpasync16(uint32_t dst, const void* src) {
    asm volatile("cp.async.cg.shared.global [%0], [%1], 16;" :: "r"(dst), "l"(src));
}
__device__ __forceinline__ void cpasync_commit() {
    asm volatile("cp.async.commit_group;");
}
__device__ __forceinline__ void cpasync_wait0() {
    asm volatile("cp.async.wait_group 0;");
}
__device__ __forceinline__ void ldsm_x4(uint32_t r[4], uint32_t a) {
    asm volatile("ldmatrix.sync.aligned.m8n8.x4.shared.b16 {%0,%1,%2,%3}, [%4];"
        : "=r"(r[0]), "=r"(r[1]), "=r"(r[2]), "=r"(r[3]) : "r"(a));
}
__device__ __forceinline__ void ldsm_x4t(uint32_t r[4], uint32_t a) {
    asm volatile("ldmatrix.sync.aligned.m8n8.x4.trans.shared.b16 {%0,%1,%2,%3}, [%4];"
        : "=r"(r[0]), "=r"(r[1]), "=r"(r[2]), "=r"(r[3]) : "r"(a));
}
__device__ __forceinline__ void mma16816(float c[4], const uint32_t a[4],
                                         uint32_t b0, uint32_t b1) {
    asm volatile(
        "mma.sync.aligned.m16n8k16.row.col.f32.f16.f16.f32 "
        "{%0,%1,%2,%3},{%4,%5,%6,%7},{%8,%9},{%0,%1,%2,%3};"
        : "+f"(c[0]), "+f"(c[1]), "+f"(c[2]), "+f"(c[3])
        : "r"(a[0]), "r"(a[1]), "r"(a[2]), "r"(a[3]), "r"(b0), "r"(b1));
}

// ---------------- 1) style modulation (64 blocks of 64 ci rows) ----------------
__global__ void __launch_bounds__(256) k_style(const float* __restrict__ style,
                                               const float* __restrict__ mw,
                                               const float* __restrict__ mb) {
    const int b = blockIdx.x >> 3;
    const int g = blockIdx.x & 7;
    const int tid = threadIdx.x;
    const int ci_l = tid >> 2;
    const int q = tid & 3;
    __shared__ float st[WDn];
    st[tid] = style[b*WDn + tid];
    st[tid + 256] = style[b*WDn + tid + 256];
    __syncthreads();
    const int ci = g*64 + ci_l;
    const float* row = mw + (size_t)ci*WDn + q*128;
    const float* sv = st + q*128;
    float acc = 0.f;
    #pragma unroll 16
    for (int w = 0; w < 128; w++) acc += sv[w] * row[w];
    acc += __shfl_xor_sync(0xffffffffu, acc, 1);
    acc += __shfl_xor_sync(0xffffffffu, acc, 2);
    if (q == 0) {
        const float eq = 0.044194173824159216f;  // 1/sqrt(512)
        g_s[b*CIn + ci] = acc * eq + mb[ci];
    }
}

// ---------------- 2) zero-padded fp16 input, row stride 72 ----------------
__global__ void k_pad(const float* __restrict__ x) {
    const int plane = blockIdx.x;          // b*CI + ci
    const float* src = x + (size_t)plane * (Hn*Hn);
    __half* dst = g_xpad + (size_t)plane * PS;
    for (int i = threadIdx.x; i < HPn*18; i += blockDim.x) {
        const int y = i / 18, x0 = (i - y*18) * 4;
        __half h[4];
        #pragma unroll
        for (int d = 0; d < 4; d++) {
            const int xx = x0 + d;
            float v = 0.f;
            if (y >= 1 && y <= Hn && xx >= 1 && xx <= Hn)
                v = src[(y-1)*Hn + (xx-1)];
            h[d] = __float2half_rn(v);
        }
        *(uint2*)(dst + y*RS + x0) = *(uint2*)h;
    }
}

// ---------------- 3) merged demod + weight write; one block per co, loop b ----------------
__global__ void __launch_bounds__(256) k_mod(const float* __restrict__ weight) {
    const int co = blockIdx.x;             // 512 blocks
    const int tid = threadIdx.x;
    __shared__ float ss[Bn*CIn];           // 16 KB: all styles
    for (int i = tid; i < Bn*CIn; i += 256) ss[i] = g_s[i];
    __syncthreads();

    const float* w = weight + (size_t)co*KTOT;
    float wv[18];
    int cidx[18];
    #pragma unroll
    for (int j = 0; j < 18; j++) {
        const int i = j*256 + tid;
        wv[j] = w[i];
        cidx[j] = i / 9;
    }
    __shared__ float red[8];
    __shared__ float s_d;

    for (int b = 0; b < Bn; b++) {
        const float* sb = ss + b*CIn;
        float v[18];
        float acc = 0.f;
        #pragma unroll
        for (int j = 0; j < 18; j++) {
            v[j] = wv[j] * sb[cidx[j]];
            acc += v[j] * v[j];
        }
        #pragma unroll
        for (int o = 16; o; o >>= 1) acc += __shfl_xor_sync(0xffffffffu, acc, o);
        if ((tid & 31) == 0) red[tid >> 5] = acc;
        __syncthreads();
        if (tid == 0) {
            float t = 0.f;
            #pragma unroll
            for (int i = 0; i < 8; i++) t += red[i];
            const float cs2 = 1.0f / (float)KTOT;
            const float CS = 0.014731391274719742f;  // 1/sqrt(4608)
            s_d = rsqrtf(cs2 * t + 1e-8f) * CS;
        }
        __syncthreads();
        const float d = s_d;
        #pragma unroll
        for (int j = 0; j < 18; j++) {
            const int i = j*256 + tid;
            const int ci = cidx[j], r = i - 9*ci;
            const int ky = r / 3, kx = r - 3*ky;
            g_wt[((size_t)(b*3 + ky)*COn + co)*KP + ci*3 + kx] = __float2half_rn(v[j] * d);
        }
        __syncthreads();
    }
}

// ---------------- 4) fp16 mma implicit-GEMM conv, 3 ky passes, occ 2, KT=96 ----------------
__global__ void __launch_bounds__(NT, 2) k_conv(const float* __restrict__ noise,
                                                const float* __restrict__ noise_w,
                                                const float* __restrict__ act_b,
                                                float* __restrict__ out) {
    extern __shared__ __align__(16) unsigned char sm[];
    const uint32_t sbase = smem_u32(sm);

    const int tid = threadIdx.x, lane = tid & 31, warp = tid >> 5;
    const int wm = warp & 1, wn = warp >> 1;        // 2 x 4 warp grid, 64x32 tiles
    const int n0 = blockIdx.x * TN;                 // hw tile (2 image rows)
    const int m0 = blockIdx.y * TM;                 // co tile
    const int b  = blockIdx.z;
    const int y0 = n0 >> 6;                         // first image row

    // B g2s map: 512 slots = 32 ci x 2 rows x 8 xs -> 2 per thread (ci, ci+16)
    const int ci_l = tid >> 4;                      // 0..15 (slot2 = ci_l+16)
    const int br = (tid >> 3) & 1;
    const int xs = tid & 7;
    const int n8 = br * 8 + xs;                     // n-chunk 0..15

    // ldmatrix per-lane offsets
    const uint32_t a_lane = (uint32_t)((wm*64 + (lane & 15)) * A_STRIDE + (lane >> 4) * 16);
    const int krow0 = lane & 15;
    const int bc0 = wn * 4 + (lane >> 4);
    const uint32_t b_off0 = (uint32_t)(krow0 * 256 + (((bc0 + 0) ^ (krow0 & 7)) & 15) * 16);
    const uint32_t b_off1 = (uint32_t)(krow0 * 256 + (((bc0 + 2) ^ (krow0 & 7)) & 15) * 16);

    float acc[4][4][4];
    #pragma unroll
    for (int i = 0; i < 4; i++)
        #pragma unroll
        for (int j = 0; j < 4; j++)
            #pragma unroll
            for (int q = 0; q < 4; q++) acc[i][j][q] = 0.f;

    uint4 wv0, wv1;
    uint32_t wx0, wx1;

    const __half* Xplane = g_xpad + (size_t)b * CIn * PS;

    // ---- A tile: cp.async, 1536 chunks of 16B -> 6 per thread ----
    auto issueA = [&](int t, int buf) {
        const int ky = t >> 4;
        const int k0 = (t & 15) * KT;
        const char* src = (const char*)(g_wt + ((size_t)(b*3 + ky)*COn + m0) * KP + k0);
        const uint32_t dst = sbase + buf * STG;
        #pragma unroll
        for (int i = 0; i < 6; i++) {
            const int c = tid + i*NT;
            const int r = c / 12, o = (c - 12*r) * 16;
            cpasync16(dst + r*A_STRIDE + o, src + (size_t)r*(KP*2) + o);
        }
        cpasync_commit();
    };
    // ---- B tile: gather 2 raw row segments into registers ----
    auto gatherB = [&](int t) {
        const int ky = t >> 4;
        const int k0 = (t & 15) * KT;
        const int cib = (k0 / 3);
        const __half* bp0 = Xplane + (size_t)(cib + ci_l) * PS + (y0 + br + ky) * RS + xs * 8;
        const __half* bp1 = bp0 + (size_t)16 * PS;
        wv0 = *(const uint4*)bp0;
        wx0 = *(const uint32_t*)(bp0 + 8);
        wv1 = *(const uint4*)bp1;
        wx1 = *(const uint32_t*)(bp1 + 8);
    };
    // ---- B tile: shift into 3 kx variants, store swizzled (2 slots) ----
    auto stageB = [&](int buf) {
        unsigned char* Bp = sm + buf * STG + AS_B;
        #pragma unroll
        for (int sl = 0; sl < 2; sl++) {
            const uint4 wv = sl ? wv1 : wv0;
            const uint32_t wx = sl ? wx1 : wx0;
            const int kb = (ci_l + sl*16) * 3;
            {
                const int k = kb;
                *(uint4*)(Bp + k*256 + (((n8 ^ (k & 7)) & 15) * 16)) = wv;
            }
            {
                const int k = kb + 1;
                uint4 v;
                v.x = __funnelshift_r(wv.x, wv.y, 16);
                v.y = __funnelshift_r(wv.y, wv.z, 16);
                v.z = __funnelshift_r(wv.z, wv.w, 16);
                v.w = __funnelshift_r(wv.w, wx,   16);
                *(uint4*)(Bp + k*256 + (((n8 ^ (k & 7)) & 15) * 16)) = v;
            }
            {
                const int k = kb + 2;
                uint4 v; v.x = wv.y; v.y = wv.z; v.z = wv.w; v.w = wx;
                *(uint4*)(Bp + k*256 + (((n8 ^ (k & 7)) & 15) * 16)) = v;
            }
        }
    };
    // ---- mma over stage buf: 64x32 warp tile, 6 k16 steps ----
    auto compute = [&](int buf) {
        const uint32_t aB = sbase + buf * STG;
        const uint32_t bB = aB + AS_B;
        #pragma unroll
        for (int kb = 0; kb < KT; kb += 16) {
            uint32_t af[4][4], bf[2][4];
            #pragma unroll
            for (int mi = 0; mi < 4; mi++)
                ldsm_x4(af[mi], aB + a_lane + mi*(16*A_STRIDE) + kb*2);
            ldsm_x4t(bf[0], bB + b_off0 + kb*256);
            ldsm_x4t(bf[1], bB + b_off1 + kb*256);
            #pragma unroll
            for (int mi = 0; mi < 4; mi++) {
                #pragma unroll
                for (int it = 0; it < 2; it++) {
                    mma16816(acc[mi][it*2 + 0], af[mi], bf[it][0], bf[it][1]);
                    mma16816(acc[mi][it*2 + 1], af[mi], bf[it][2], bf[it][3]);
                }
            }
        }
    };

    // prologue: stage 0 -> buf 0
    issueA(0, 0);
    gatherB(0);
    stageB(0);
    cpasync_wait0();
    __syncthreads();

    for (int t = 0; t < NSTAGE; t++) {
        if (t + 1 < NSTAGE) {
            issueA(t + 1, (t + 1) & 1);
            gatherB(t + 1);
        }
        compute(t & 1);
        if (t + 1 < NSTAGE) {
            stageB((t + 1) & 1);
            cpasync_wait0();
            __syncthreads();
        }
    }

    // fused epilogue: + noise_w*noise + bias, leaky_relu(0.2) * sqrt(2)
    const int gr = lane >> 2, tg = lane & 3;
    const float nw = noise_w[0];
    const float SQ2 = 1.4142135623730951f;
    #pragma unroll
    for (int mi = 0; mi < 4; mi++) {
        #pragma unroll
        for (int h = 0; h < 2; h++) {
            const int co = m0 + wm*64 + mi*16 + gr + 8*h;
            const float bias = act_b[co];
            const float* np = noise + (size_t)(b*COn + co) * (Hn*Hn);
            float* op = out + (size_t)(b*COn + co) * (Hn*Hn);
            #pragma unroll
            for (int ni = 0; ni < 4; ni++) {
                const int n = n0 + wn*32 + ni*8 + tg*2;
                float2 nv = *(const float2*)(np + n);
                float v0 = acc[mi][ni][2*h + 0] + nw * nv.x + bias;
                float v1 = acc[mi][ni][2*h + 1] + nw * nv.y + bias;
                float2 ov;
                ov.x = (v0 > 0.f ? v0 : 0.2f*v0) * SQ2;
                ov.y = (v1 > 0.f ? v1 : 0.2f*v1) * SQ2;
                *(float2*)(op + n) = ov;
            }
        }
    }
}

// ---------------- launch ----------------
extern "C" void kernel_launch(void* const* d_in, const int* in_sizes, int n_in,
                              void* d_out, int out_size) {
    (void)in_sizes; (void)n_in; (void)out_size;
    const float* x        = (const float*)d_in[0];  // [8,512,64,64]
    const float* style    = (const float*)d_in[1];  // [8,512]
    const float* noise    = (const float*)d_in[2];  // [8,512,64,64]
    const float* weight   = (const float*)d_in[3];  // [1,512,512,3,3]
    const float* mod_w    = (const float*)d_in[4];  // [512,512]
    const float* mod_b    = (const float*)d_in[5];  // [512]
    const float* noise_w  = (const float*)d_in[6];  // [1]
    const float* act_b    = (const float*)d_in[7];  // [512]
    float* out = (float*)d_out;

    cudaFuncSetAttribute(k_conv, cudaFuncAttributeMaxDynamicSharedMemorySize, SMEM_TOTAL);

    k_style<<<Bn*8, 256>>>(style, mod_w, mod_b);
    k_pad<<<Bn*CIn, 256>>>(x);
    k_mod<<<COn, 256>>>(weight);
    dim3 gc((Hn*Hn)/TN, COn/TM, Bn);
    k_conv<<<gc, NT, SMEM_TOTAL>>>(noise, noise_w, act_b, out);
}